// round 12
// baseline (speedup 1.0000x reference)
#include <cuda_runtime.h>
#include <cuda_fp16.h>
#include <cstdint>

#define NN   100000
#define NE   1600000
#define ALPHA_C 0.1f
#define COEF_C  0.3f            // (1-ALPHA)/K = 0.9/3

// ---------------- scratch (device globals: no allocation allowed) ----------------
__device__ int   g_is64;             // 1 if edge_index is int64, 0 if int32
__device__ int   g_cnt[NN];          // in-degree (original edges)
__device__ int   g_rowptr[NN + 1];   // CSR row pointers by dst
__device__ int   g_cursor[NN];       // scatter cursors
__device__ float g_dinv[NN];         // 1/sqrt(deg+1)
__device__ int   g_part[128];        // scan partials (98 blocks)
__device__ int   g_src[NE];          // CSR: src per edge (sorted by dst), 4B
__device__ uint4 g_xh [NN * 8];      // dinv*x  in fp16 (row = 8 uint4 = 128B)
__device__ uint4 g_h1 [NN * 8];      // dinv*h1 in fp16
__device__ uint4 g_h2 [NN * 8];      // dinv*h2 in fp16
__device__ uint4 g_ach[NN * 8];      // relu(out) in fp16 (for mean pass)

// ---------------- fp16 pack/unpack helpers ----------------
__device__ __forceinline__ void unpack8(uint4 v, float* f) {
    float2 t;
    t = __half22float2(*(__half2*)&v.x); f[0] = t.x; f[1] = t.y;
    t = __half22float2(*(__half2*)&v.y); f[2] = t.x; f[3] = t.y;
    t = __half22float2(*(__half2*)&v.z); f[4] = t.x; f[5] = t.y;
    t = __half22float2(*(__half2*)&v.w); f[6] = t.x; f[7] = t.y;
}
__device__ __forceinline__ uint4 pack8(const float* f) {
    uint4 u; __half2 h;
    h = __floats2half2_rn(f[0], f[1]); u.x = *(unsigned*)&h;
    h = __floats2half2_rn(f[2], f[3]); u.y = *(unsigned*)&h;
    h = __floats2half2_rn(f[4], f[5]); u.z = *(unsigned*)&h;
    h = __floats2half2_rn(f[6], f[7]); u.w = *(unsigned*)&h;
    return u;
}

// ---------------- prep: zero counters, detect edge dtype ----------------
__global__ void k_prep(const int* __restrict__ ei32) {
    int i = blockIdx.x * blockDim.x + threadIdx.x;
    if (i < NN) g_cnt[i] = 0;
    if (i == 0) {
        // int64 little-endian with values < 100000 -> every odd 32-bit word is 0
        int zeros = 0;
        #pragma unroll 1
        for (int k = 1; k < 129; k += 2) zeros += (ei32[k] == 0);
        g_is64 = (zeros >= 60) ? 1 : 0;
        g_rowptr[NN] = NE;
    }
}

// ---------------- CSR build ----------------
__global__ void k_hist(const void* __restrict__ ei) {
    int e = blockIdx.x * blockDim.x + threadIdx.x;
    int is64 = g_is64;
    if (e < NE) {
        int dst = is64 ? ((const int*)ei)[2 * ((long long)NE + e)]
                       : ((const int*)ei)[NE + e];
        atomicAdd(&g_cnt[dst], 1);
    }
}

// 1024-thread block scan via shuffles (2 barriers)
__global__ void k_scan_local() {
    __shared__ int wsum[32];
    int tid  = threadIdx.x;
    int lane = tid & 31, wid = tid >> 5;
    int i = blockIdx.x * 1024 + tid;
    int v = (i < NN) ? g_cnt[i] : 0;
    int s = v;
    #pragma unroll
    for (int off = 1; off < 32; off <<= 1) {
        int t = __shfl_up_sync(0xffffffffu, s, off);
        if (lane >= off) s += t;
    }
    if (lane == 31) wsum[wid] = s;
    __syncthreads();
    if (wid == 0) {
        int ws = wsum[lane];
        #pragma unroll
        for (int off = 1; off < 32; off <<= 1) {
            int t = __shfl_up_sync(0xffffffffu, ws, off);
            if (lane >= off) ws += t;
        }
        wsum[lane] = ws;
    }
    __syncthreads();
    int incl = s + (wid ? wsum[wid - 1] : 0);
    if (i < NN) g_rowptr[i] = incl - v;     // local exclusive
    if (tid == 1023) g_part[blockIdx.x] = incl;
}

// finalize: shuffle-scan the 98 partials per block, fix rowptr/cursor/dinv,
// AND convert x -> fp16 pre-scaled by dinv[row].  grid = NN*8 threads.
__global__ void k_finalize(const float* __restrict__ x) {
    __shared__ int wsum[8];
    __shared__ int sp[128];
    int tid  = threadIdx.x;
    int lane = tid & 31, wid = tid >> 5;
    if (tid < 128) {
        int pv = (tid < 98) ? g_part[tid] : 0;
        int s = pv;
        #pragma unroll
        for (int off = 1; off < 32; off <<= 1) {
            int t = __shfl_up_sync(0xffffffffu, s, off);
            if (lane >= off) s += t;
        }
        if (lane == 31) wsum[wid] = s;
        sp[tid] = s - pv;   // warp-local exclusive
    }
    __syncthreads();
    if (tid < 128) {
        int base = 0;
        #pragma unroll
        for (int w = 0; w < 4; w++) base += (wid > w) ? wsum[w] : 0;
        sp[tid] += base;
    }
    __syncthreads();

    int j = blockIdx.x * blockDim.x + threadIdx.x;
    if (j < NN) {
        int rp = g_rowptr[j] + sp[j >> 10];
        g_rowptr[j] = rp;
        g_cursor[j] = rp;
        g_dinv[j] = rsqrtf((float)(g_cnt[j] + 1));   // +1 self loop
    }
    if (j < NN * 8) {
        int row = j >> 3;
        float dv = rsqrtf((float)(__ldg(&g_cnt[row]) + 1));
        float4 p0 = __ldg(&((const float4*)x)[j * 2]);
        float4 p1 = __ldg(&((const float4*)x)[j * 2 + 1]);
        float f[8] = { dv*p0.x, dv*p0.y, dv*p0.z, dv*p0.w,
                       dv*p1.x, dv*p1.y, dv*p1.z, dv*p1.w };
        g_xh[j] = pack8(f);
    }
}

__global__ void k_scatter(const void* __restrict__ ei) {
    int e = blockIdx.x * blockDim.x + threadIdx.x;
    int is64 = g_is64;
    if (e < NE) {
        int src, dst;
        if (is64) {
            src = ((const int*)ei)[2 * (long long)e];
            dst = ((const int*)ei)[2 * ((long long)NE + e)];
        } else {
            src = ((const int*)ei)[e];
            dst = ((const int*)ei)[NE + e];
        }
        int pos = atomicAdd(&g_cursor[dst], 1);
        g_src[pos] = src;
    }
}

// ---------------- propagation: warp = 4 x 8-lane groups -------------------------
// Main loop: 8 edges/iter (2 per group) with dual accumulator chains and NO masks;
// short masked remainder loop (<=2 iters) for the tail.
// Rows pre-scaled: stored v = dinv*h.  t = sum v[src] + v[row].
// PASS 1: xh -> h1 = pack(dv^2 * t)
// PASS 2: h1 -> h2 = pack(dv^2 * t)
// PASS 3: h2 -> g_ach = relu(0.1x + 0.3*rdv*(v1+v2) + 0.3*dv*t)
template <int PASS>
__global__ void k_spmm(const float* __restrict__ x) {
    int row  = blockIdx.x * (blockDim.x >> 5) + (threadIdx.x >> 5);
    if (row >= NN) return;
    int lane = threadIdx.x & 31;
    int sub  = lane >> 3;       // edge slot 0..3
    int l    = lane & 7;        // uint4 index within 128B row

    const uint4* hin = (PASS == 1) ? g_xh : (PASS == 2) ? g_h1 : g_h2;

    int beg = g_rowptr[row];
    int end = g_rowptr[row + 1];
    float dv = g_dinv[row];

    float a[8];
    {   // self term: + v[row], counted once (sub 0)
        uint4 sv = __ldg(&hin[row * 8 + l]);
        float f[8]; unpack8(sv, f);
        float m0 = (sub == 0) ? 1.f : 0.f;
        #pragma unroll
        for (int i = 0; i < 8; i++) a[i] = m0 * f[i];
    }

    int e = beg;
    // unroll-by-2: two independent gathers in flight per group, mask-free
    for (; e + 8 <= end; e += 8) {
        int s0 = __ldg(&g_src[e + sub]);
        int s1 = __ldg(&g_src[e + 4 + sub]);
        uint4 v0 = __ldg(&hin[s0 * 8 + l]);
        uint4 v1 = __ldg(&hin[s1 * 8 + l]);
        float f0[8], f1[8];
        unpack8(v0, f0);
        unpack8(v1, f1);
        #pragma unroll
        for (int i = 0; i < 8; i++) a[i] += f0[i] + f1[i];
    }
    // remainder (< 8 edges): masked, group-uniform
    for (; e < end; e += 4) {
        int ee = e + sub;
        int s = (ee < end) ? __ldg(&g_src[ee]) : row;
        float m = (ee < end) ? 1.f : 0.f;
        uint4 v = __ldg(&hin[s * 8 + l]);
        float f[8]; unpack8(v, f);
        #pragma unroll
        for (int i = 0; i < 8; i++) a[i] = fmaf(m, f[i], a[i]);
    }

    #pragma unroll
    for (int i = 0; i < 8; i++) {
        a[i] += __shfl_xor_sync(0xffffffffu, a[i], 8);
        a[i] += __shfl_xor_sync(0xffffffffu, a[i], 16);
    }

    if (sub == 0) {
        int o = row * 8 + l;
        if (PASS != 3) {
            float hv[8]; float dv2 = dv * dv;
            #pragma unroll
            for (int i = 0; i < 8; i++) hv[i] = dv2 * a[i];
            ((PASS == 1) ? g_h1 : g_h2)[o] = pack8(hv);
        } else {
            // out = 0.1x + 0.3*(h1 + h2 + h3); stored v = dinv*h so h = rdv*v
            float rdv = __frcp_rn(dv);
            float c1 = COEF_C * rdv;      // for v1+v2
            float c3 = COEF_C * dv;       // h3 = dv * t
            float v1[8], v2[8];
            unpack8(__ldg(&g_h1[o]), v1);
            unpack8(__ldg(&g_h2[o]), v2);
            float4 x0 = __ldg(&((const float4*)x)[o * 2]);
            float4 x1 = __ldg(&((const float4*)x)[o * 2 + 1]);
            float xf[8] = { x0.x, x0.y, x0.z, x0.w, x1.x, x1.y, x1.z, x1.w };
            float rv[8];
            #pragma unroll
            for (int i = 0; i < 8; i++) {
                float t = ALPHA_C * xf[i] + c1 * (v1[i] + v2[i]) + c3 * a[i];
                rv[i] = fmaxf(t, 0.f);
            }
            g_ach[o] = pack8(rv);
        }
    }
}

// mean conv over original edges on relu(out) (pre-relu'd fp16) + residual + relu
__global__ void k_mean(const float* __restrict__ x, float* __restrict__ out) {
    int row  = blockIdx.x * (blockDim.x >> 5) + (threadIdx.x >> 5);
    if (row >= NN) return;
    int lane = threadIdx.x & 31;
    int sub  = lane >> 3;
    int l    = lane & 7;

    int beg = g_rowptr[row];
    int end = g_rowptr[row + 1];

    float a[8] = {0.f, 0.f, 0.f, 0.f, 0.f, 0.f, 0.f, 0.f};

    int e = beg;
    for (; e + 8 <= end; e += 8) {
        int s0 = __ldg(&g_src[e + sub]);
        int s1 = __ldg(&g_src[e + 4 + sub]);
        uint4 v0 = __ldg(&g_ach[s0 * 8 + l]);
        uint4 v1 = __ldg(&g_ach[s1 * 8 + l]);
        float f0[8], f1[8];
        unpack8(v0, f0);
        unpack8(v1, f1);
        #pragma unroll
        for (int i = 0; i < 8; i++) a[i] += f0[i] + f1[i];
    }
    for (; e < end; e += 4) {
        int ee = e + sub;
        int s = (ee < end) ? __ldg(&g_src[ee]) : row;
        float m = (ee < end) ? 1.f : 0.f;
        uint4 v = __ldg(&g_ach[s * 8 + l]);
        float f[8]; unpack8(v, f);
        #pragma unroll
        for (int i = 0; i < 8; i++) a[i] = fmaf(m, f[i], a[i]);
    }

    #pragma unroll
    for (int i = 0; i < 8; i++) {
        a[i] += __shfl_xor_sync(0xffffffffu, a[i], 8);
        a[i] += __shfl_xor_sync(0xffffffffu, a[i], 16);
    }

    if (sub == 0) {
        float inv = 1.0f / fmaxf((float)(end - beg), 1.0f);
        int o = row * 8 + l;
        float4 x0 = __ldg(&((const float4*)x)[o * 2]);
        float4 x1 = __ldg(&((const float4*)x)[o * 2 + 1]);
        float4 r0, r1;
        r0.x = fmaxf(a[0] * inv + x0.x, 0.f);
        r0.y = fmaxf(a[1] * inv + x0.y, 0.f);
        r0.z = fmaxf(a[2] * inv + x0.z, 0.f);
        r0.w = fmaxf(a[3] * inv + x0.w, 0.f);
        r1.x = fmaxf(a[4] * inv + x1.x, 0.f);
        r1.y = fmaxf(a[5] * inv + x1.y, 0.f);
        r1.z = fmaxf(a[6] * inv + x1.z, 0.f);
        r1.w = fmaxf(a[7] * inv + x1.w, 0.f);
        ((float4*)out)[o * 2]     = r0;
        ((float4*)out)[o * 2 + 1] = r1;
    }
}

// ---------------- launch ----------------
extern "C" void kernel_launch(void* const* d_in, const int* in_sizes, int n_in,
                              void* d_out, int out_size) {
    const float* x  = (const float*)d_in[0];
    const void*  ei = (const void*)d_in[1];
    float* out = (float*)d_out;

    k_prep<<<(NN + 255) / 256, 256>>>((const int*)ei);
    k_hist<<<(NE + 255) / 256, 256>>>(ei);
    int nb = (NN + 1023) / 1024;   // 98
    k_scan_local<<<nb, 1024>>>();
    k_finalize<<<(NN * 8 + 255) / 256, 256>>>(x);
    k_scatter<<<(NE + 255) / 256, 256>>>(ei);

    const int WPB = 8;                        // warps (rows) per block
    int grid = (NN + WPB - 1) / WPB;          // 12500
    // SSG hops: out = 0.1*x + 0.3*(A x + A^2 x + A^3 x), acc-free
    k_spmm<1><<<grid, WPB * 32>>>(x);         // xh -> h1
    k_spmm<2><<<grid, WPB * 32>>>(x);         // h1 -> h2
    k_spmm<3><<<grid, WPB * 32>>>(x);         // h2 -> relu(out) -> g_ach
    // mean conv on relu(out) + residual + relu
    k_mean<<<grid, WPB * 32>>>(x, out);
}

// round 13
// speedup vs baseline: 1.1147x; 1.1147x over previous
#include <cuda_runtime.h>
#include <cuda_fp16.h>
#include <cstdint>

#define NN   100000
#define NE   1600000
#define ALPHA_C 0.1f
#define COEF_C  0.3f            // (1-ALPHA)/K = 0.9/3

// ---------------- scratch (device globals: no allocation allowed) ----------------
__device__ int   g_is64;             // 1 if edge_index is int64, 0 if int32
__device__ int   g_cnt[NN];          // in-degree (original edges)
__device__ int   g_rowptr[NN + 1];   // CSR row pointers by dst
__device__ float g_dinv[NN];         // 1/sqrt(deg+1)
__device__ int   g_part[128];        // scan partials (98 blocks)
__device__ int   g_eoff[NE];         // per-edge local offset within its dst row
__device__ int   g_src[NE];          // CSR: src per edge (sorted by dst), 4B
__device__ uint4 g_xh [NN * 8];      // dinv*x  in fp16 (row = 8 uint4 = 128B)
__device__ uint4 g_h1 [NN * 8];      // dinv*h1 in fp16
__device__ uint4 g_h2 [NN * 8];      // dinv*h2 in fp16
__device__ uint4 g_ach[NN * 8];      // relu(out) in fp16 (for mean pass)

// ---------------- fp16 pack/unpack helpers ----------------
__device__ __forceinline__ void unpack8(uint4 v, float* f) {
    float2 t;
    t = __half22float2(*(__half2*)&v.x); f[0] = t.x; f[1] = t.y;
    t = __half22float2(*(__half2*)&v.y); f[2] = t.x; f[3] = t.y;
    t = __half22float2(*(__half2*)&v.z); f[4] = t.x; f[5] = t.y;
    t = __half22float2(*(__half2*)&v.w); f[6] = t.x; f[7] = t.y;
}
__device__ __forceinline__ uint4 pack8(const float* f) {
    uint4 u; __half2 h;
    h = __floats2half2_rn(f[0], f[1]); u.x = *(unsigned*)&h;
    h = __floats2half2_rn(f[2], f[3]); u.y = *(unsigned*)&h;
    h = __floats2half2_rn(f[4], f[5]); u.z = *(unsigned*)&h;
    h = __floats2half2_rn(f[6], f[7]); u.w = *(unsigned*)&h;
    return u;
}

// ---------------- prep: zero counters, detect edge dtype ----------------
__global__ void k_prep(const int* __restrict__ ei32) {
    int i = blockIdx.x * blockDim.x + threadIdx.x;
    if (i < NN) g_cnt[i] = 0;
    if (i == 0) {
        // int64 little-endian with values < 100000 -> every odd 32-bit word is 0
        int zeros = 0;
        #pragma unroll 1
        for (int k = 1; k < 129; k += 2) zeros += (ei32[k] == 0);
        g_is64 = (zeros >= 60) ? 1 : 0;
        g_rowptr[NN] = NE;
    }
}

// ---------------- CSR build ----------------
// hist also records each edge's local offset (the atomicAdd return) so the
// scatter pass needs no atomics at all.
__global__ void k_hist(const void* __restrict__ ei) {
    int e = blockIdx.x * blockDim.x + threadIdx.x;
    int is64 = g_is64;
    if (e < NE) {
        int dst = is64 ? ((const int*)ei)[2 * ((long long)NE + e)]
                       : ((const int*)ei)[NE + e];
        g_eoff[e] = atomicAdd(&g_cnt[dst], 1);
    }
}

// 1024-thread block scan via shuffles (2 barriers)
__global__ void k_scan_local() {
    __shared__ int wsum[32];
    int tid  = threadIdx.x;
    int lane = tid & 31, wid = tid >> 5;
    int i = blockIdx.x * 1024 + tid;
    int v = (i < NN) ? g_cnt[i] : 0;
    int s = v;
    #pragma unroll
    for (int off = 1; off < 32; off <<= 1) {
        int t = __shfl_up_sync(0xffffffffu, s, off);
        if (lane >= off) s += t;
    }
    if (lane == 31) wsum[wid] = s;
    __syncthreads();
    if (wid == 0) {
        int ws = wsum[lane];
        #pragma unroll
        for (int off = 1; off < 32; off <<= 1) {
            int t = __shfl_up_sync(0xffffffffu, ws, off);
            if (lane >= off) ws += t;
        }
        wsum[lane] = ws;
    }
    __syncthreads();
    int incl = s + (wid ? wsum[wid - 1] : 0);
    if (i < NN) g_rowptr[i] = incl - v;     // local exclusive
    if (tid == 1023) g_part[blockIdx.x] = incl;
}

// finalize: shuffle-scan the 98 partials per block, fix rowptr/dinv,
// AND convert x -> fp16 pre-scaled by dinv[row].  grid = NN*8 threads.
__global__ void k_finalize(const float* __restrict__ x) {
    __shared__ int wsum[8];
    __shared__ int sp[128];
    int tid  = threadIdx.x;
    int lane = tid & 31, wid = tid >> 5;
    if (tid < 128) {
        int pv = (tid < 98) ? g_part[tid] : 0;
        int s = pv;
        #pragma unroll
        for (int off = 1; off < 32; off <<= 1) {
            int t = __shfl_up_sync(0xffffffffu, s, off);
            if (lane >= off) s += t;
        }
        if (lane == 31) wsum[wid] = s;
        sp[tid] = s - pv;   // warp-local exclusive
    }
    __syncthreads();
    if (tid < 128) {
        int base = 0;
        #pragma unroll
        for (int w = 0; w < 4; w++) base += (wid > w) ? wsum[w] : 0;
        sp[tid] += base;
    }
    __syncthreads();

    int j = blockIdx.x * blockDim.x + threadIdx.x;
    if (j < NN) {
        g_rowptr[j] += sp[j >> 10];
        g_dinv[j] = rsqrtf((float)(g_cnt[j] + 1));   // +1 self loop
    }
    if (j < NN * 8) {
        int row = j >> 3;
        float dv = rsqrtf((float)(__ldg(&g_cnt[row]) + 1));
        float4 p0 = __ldg(&((const float4*)x)[j * 2]);
        float4 p1 = __ldg(&((const float4*)x)[j * 2 + 1]);
        float f[8] = { dv*p0.x, dv*p0.y, dv*p0.z, dv*p0.w,
                       dv*p1.x, dv*p1.y, dv*p1.z, dv*p1.w };
        g_xh[j] = pack8(f);
    }
}

// atomic-free scatter: slot = rowptr[dst] + saved local offset
__global__ void k_scatter(const void* __restrict__ ei) {
    int e = blockIdx.x * blockDim.x + threadIdx.x;
    int is64 = g_is64;
    if (e < NE) {
        int src, dst;
        if (is64) {
            src = ((const int*)ei)[2 * (long long)e];
            dst = ((const int*)ei)[2 * ((long long)NE + e)];
        } else {
            src = ((const int*)ei)[e];
            dst = ((const int*)ei)[NE + e];
        }
        int pos = __ldg(&g_rowptr[dst]) + g_eoff[e];
        g_src[pos] = src;
    }
}

// ---------------- propagation: warp = 4 x 8-lane groups, 4 edges/iter ----------
// Rows pre-scaled: stored v = dinv*h.  t = sum v[src] + v[row].
// PASS 1: xh -> h1 = pack(dv^2 * t)
// PASS 2: h1 -> h2 = pack(dv^2 * t)
// PASS 3: h2 -> g_ach = relu(0.1x + 0.3*rdv*(v1+v2) + 0.3*dv*t)
template <int PASS>
__global__ void k_spmm(const float* __restrict__ x) {
    int row  = blockIdx.x * (blockDim.x >> 5) + (threadIdx.x >> 5);
    if (row >= NN) return;
    int lane = threadIdx.x & 31;
    int sub  = lane >> 3;       // edge slot 0..3
    int l    = lane & 7;        // uint4 index within 128B row

    const uint4* hin = (PASS == 1) ? g_xh : (PASS == 2) ? g_h1 : g_h2;

    int beg = g_rowptr[row];
    int end = g_rowptr[row + 1];
    float dv = g_dinv[row];

    float a[8];
    {   // self term: + v[row], counted once (sub 0)
        uint4 sv = __ldg(&hin[row * 8 + l]);
        float f[8]; unpack8(sv, f);
        float m0 = (sub == 0) ? 1.f : 0.f;
        #pragma unroll
        for (int i = 0; i < 8; i++) a[i] = m0 * f[i];
    }

    // simple loop with index-only prefetch (gather consumed immediately)
    int e  = beg;
    int ee = e + sub;
    int s  = (ee < end) ? __ldg(&g_src[ee]) : row;
    float m = (ee < end) ? 1.f : 0.f;
    while (e < end) {
        int en = e + 4;
        int s2 = row; float m2 = 0.f;
        int ee2 = en + sub;
        if (ee2 < end) { s2 = __ldg(&g_src[ee2]); m2 = 1.f; }
        uint4 v = __ldg(&hin[s * 8 + l]);
        float f[8]; unpack8(v, f);
        #pragma unroll
        for (int i = 0; i < 8; i++) a[i] = fmaf(m, f[i], a[i]);
        s = s2; m = m2; e = en;
    }

    #pragma unroll
    for (int i = 0; i < 8; i++) {
        a[i] += __shfl_xor_sync(0xffffffffu, a[i], 8);
        a[i] += __shfl_xor_sync(0xffffffffu, a[i], 16);
    }

    if (sub == 0) {
        int o = row * 8 + l;
        if (PASS != 3) {
            float hv[8]; float dv2 = dv * dv;
            #pragma unroll
            for (int i = 0; i < 8; i++) hv[i] = dv2 * a[i];
            ((PASS == 1) ? g_h1 : g_h2)[o] = pack8(hv);
        } else {
            // out = 0.1x + 0.3*(h1 + h2 + h3); stored v = dinv*h so h = rdv*v
            float rdv = __frcp_rn(dv);
            float c1 = COEF_C * rdv;      // for v1+v2
            float c3 = COEF_C * dv;       // h3 = dv * t
            float v1[8], v2[8];
            unpack8(__ldg(&g_h1[o]), v1);
            unpack8(__ldg(&g_h2[o]), v2);
            float4 x0 = __ldg(&((const float4*)x)[o * 2]);
            float4 x1 = __ldg(&((const float4*)x)[o * 2 + 1]);
            float xf[8] = { x0.x, x0.y, x0.z, x0.w, x1.x, x1.y, x1.z, x1.w };
            float rv[8];
            #pragma unroll
            for (int i = 0; i < 8; i++) {
                float t = ALPHA_C * xf[i] + c1 * (v1[i] + v2[i]) + c3 * a[i];
                rv[i] = fmaxf(t, 0.f);
            }
            g_ach[o] = pack8(rv);
        }
    }
}

// mean conv over original edges on relu(out) (pre-relu'd fp16) + residual + relu
__global__ void k_mean(const float* __restrict__ x, float* __restrict__ out) {
    int row  = blockIdx.x * (blockDim.x >> 5) + (threadIdx.x >> 5);
    if (row >= NN) return;
    int lane = threadIdx.x & 31;
    int sub  = lane >> 3;
    int l    = lane & 7;

    int beg = g_rowptr[row];
    int end = g_rowptr[row + 1];

    float a[8] = {0.f, 0.f, 0.f, 0.f, 0.f, 0.f, 0.f, 0.f};

    int e  = beg;
    int ee = e + sub;
    int s  = (ee < end) ? __ldg(&g_src[ee]) : row;
    float m = (ee < end) ? 1.f : 0.f;
    while (e < end) {
        int en = e + 4;
        int s2 = row; float m2 = 0.f;
        int ee2 = en + sub;
        if (ee2 < end) { s2 = __ldg(&g_src[ee2]); m2 = 1.f; }
        uint4 v = __ldg(&g_ach[s * 8 + l]);
        float f[8]; unpack8(v, f);
        #pragma unroll
        for (int i = 0; i < 8; i++) a[i] = fmaf(m, f[i], a[i]);
        s = s2; m = m2; e = en;
    }

    #pragma unroll
    for (int i = 0; i < 8; i++) {
        a[i] += __shfl_xor_sync(0xffffffffu, a[i], 8);
        a[i] += __shfl_xor_sync(0xffffffffu, a[i], 16);
    }

    if (sub == 0) {
        float inv = 1.0f / fmaxf((float)(end - beg), 1.0f);
        int o = row * 8 + l;
        float4 x0 = __ldg(&((const float4*)x)[o * 2]);
        float4 x1 = __ldg(&((const float4*)x)[o * 2 + 1]);
        float4 r0, r1;
        r0.x = fmaxf(a[0] * inv + x0.x, 0.f);
        r0.y = fmaxf(a[1] * inv + x0.y, 0.f);
        r0.z = fmaxf(a[2] * inv + x0.z, 0.f);
        r0.w = fmaxf(a[3] * inv + x0.w, 0.f);
        r1.x = fmaxf(a[4] * inv + x1.x, 0.f);
        r1.y = fmaxf(a[5] * inv + x1.y, 0.f);
        r1.z = fmaxf(a[6] * inv + x1.z, 0.f);
        r1.w = fmaxf(a[7] * inv + x1.w, 0.f);
        ((float4*)out)[o * 2]     = r0;
        ((float4*)out)[o * 2 + 1] = r1;
    }
}

// ---------------- launch ----------------
extern "C" void kernel_launch(void* const* d_in, const int* in_sizes, int n_in,
                              void* d_out, int out_size) {
    const float* x  = (const float*)d_in[0];
    const void*  ei = (const void*)d_in[1];
    float* out = (float*)d_out;

    k_prep<<<(NN + 255) / 256, 256>>>((const int*)ei);
    k_hist<<<(NE + 255) / 256, 256>>>(ei);
    int nb = (NN + 1023) / 1024;   // 98
    k_scan_local<<<nb, 1024>>>();
    k_finalize<<<(NN * 8 + 255) / 256, 256>>>(x);
    k_scatter<<<(NE + 255) / 256, 256>>>(ei);

    const int WPB = 8;                        // warps (rows) per block
    int grid = (NN + WPB - 1) / WPB;          // 12500
    // SSG hops: out = 0.1*x + 0.3*(A x + A^2 x + A^3 x), acc-free
    k_spmm<1><<<grid, WPB * 32>>>(x);         // xh -> h1
    k_spmm<2><<<grid, WPB * 32>>>(x);         // h1 -> h2
    k_spmm<3><<<grid, WPB * 32>>>(x);         // h2 -> relu(out) -> g_ach
    // mean conv on relu(out) + residual + relu
    k_mean<<<grid, WPB * 32>>>(x, out);
}

// round 14
// speedup vs baseline: 1.1275x; 1.0115x over previous
#include <cuda_runtime.h>
#include <cuda_fp16.h>
#include <cstdint>

#define NN   100000
#define NE   1600000
#define ALPHA_C 0.1f
#define COEF_C  0.3f            // (1-ALPHA)/K = 0.9/3

// ---------------- scratch (device globals: no allocation allowed) ----------------
__device__ int   g_is64;             // 1 if edge_index is int64, 0 if int32
__device__ int   g_cnt[NN];          // in-degree; zero-init at load, re-zeroed in scan
__device__ int   g_rowptr[NN + 1];   // CSR row pointers by dst
__device__ float g_dinv[NN];         // 1/sqrt(deg+1)
__device__ int   g_part[128];        // scan partials (98 blocks)
__device__ int   g_eoff[NE];         // packed (dst<<10 | local offset) per edge
__device__ int   g_src[NE];          // CSR: src per edge (sorted by dst), 4B
__device__ uint4 g_xh [NN * 8];      // dinv*x  in fp16 (row = 8 uint4 = 128B)
__device__ uint4 g_h1 [NN * 8];      // dinv*h1 in fp16
__device__ uint4 g_h2 [NN * 8];      // dinv*h2 in fp16
__device__ uint4 g_ach[NN * 8];      // relu(out) in fp16 (for mean pass)

// ---------------- fp16 pack/unpack helpers ----------------
__device__ __forceinline__ void unpack8(uint4 v, float* f) {
    float2 t;
    t = __half22float2(*(__half2*)&v.x); f[0] = t.x; f[1] = t.y;
    t = __half22float2(*(__half2*)&v.y); f[2] = t.x; f[3] = t.y;
    t = __half22float2(*(__half2*)&v.z); f[4] = t.x; f[5] = t.y;
    t = __half22float2(*(__half2*)&v.w); f[6] = t.x; f[7] = t.y;
}
__device__ __forceinline__ uint4 pack8(const float* f) {
    uint4 u; __half2 h;
    h = __floats2half2_rn(f[0], f[1]); u.x = *(unsigned*)&h;
    h = __floats2half2_rn(f[2], f[3]); u.y = *(unsigned*)&h;
    h = __floats2half2_rn(f[4], f[5]); u.z = *(unsigned*)&h;
    h = __floats2half2_rn(f[6], f[7]); u.w = *(unsigned*)&h;
    return u;
}

// ---------------- prep: detect edge dtype (single block) ----------------
__global__ void k_prep(const int* __restrict__ ei32) {
    if (threadIdx.x == 0) {
        // int64 little-endian with values < 100000 -> every odd 32-bit word is 0
        int zeros = 0;
        #pragma unroll 1
        for (int k = 1; k < 129; k += 2) zeros += (ei32[k] == 0);
        g_is64 = (zeros >= 60) ? 1 : 0;
        g_rowptr[NN] = NE;
    }
}

// ---------------- CSR build ----------------
// hist records packed (dst, local offset) so scatter needs no atomics and
// never re-reads the dst half of edge_index.
__global__ void k_hist(const void* __restrict__ ei) {
    int e = blockIdx.x * blockDim.x + threadIdx.x;
    int is64 = g_is64;
    if (e < NE) {
        int dst = is64 ? ((const int*)ei)[2 * ((long long)NE + e)]
                       : ((const int*)ei)[NE + e];
        int off = atomicAdd(&g_cnt[dst], 1);
        g_eoff[e] = (dst << 10) | off;     // off < 1024 (Poisson(16) degrees)
    }
}

// 1024-thread block scan via shuffles; also computes dinv and re-zeroes cnt
__global__ void k_scan_local() {
    __shared__ int wsum[32];
    int tid  = threadIdx.x;
    int lane = tid & 31, wid = tid >> 5;
    int i = blockIdx.x * 1024 + tid;
    int v = (i < NN) ? g_cnt[i] : 0;
    int s = v;
    #pragma unroll
    for (int off = 1; off < 32; off <<= 1) {
        int t = __shfl_up_sync(0xffffffffu, s, off);
        if (lane >= off) s += t;
    }
    if (lane == 31) wsum[wid] = s;
    __syncthreads();
    if (wid == 0) {
        int ws = wsum[lane];
        #pragma unroll
        for (int off = 1; off < 32; off <<= 1) {
            int t = __shfl_up_sync(0xffffffffu, ws, off);
            if (lane >= off) ws += t;
        }
        wsum[lane] = ws;
    }
    __syncthreads();
    int incl = s + (wid ? wsum[wid - 1] : 0);
    if (i < NN) {
        g_rowptr[i] = incl - v;             // local exclusive
        g_dinv[i] = rsqrtf((float)(v + 1)); // +1 self loop
        g_cnt[i] = 0;                       // clean for next replay
    }
    if (tid == 1023) g_part[blockIdx.x] = incl;
}

// finalize: shuffle-scan the 98 partials per block, fix rowptr,
// AND convert x -> fp16 pre-scaled by dinv[row].  grid = NN*8 threads.
__global__ void k_finalize(const float* __restrict__ x) {
    __shared__ int wsum[8];
    __shared__ int sp[128];
    int tid  = threadIdx.x;
    int lane = tid & 31, wid = tid >> 5;
    if (tid < 128) {
        int pv = (tid < 98) ? g_part[tid] : 0;
        int s = pv;
        #pragma unroll
        for (int off = 1; off < 32; off <<= 1) {
            int t = __shfl_up_sync(0xffffffffu, s, off);
            if (lane >= off) s += t;
        }
        if (lane == 31) wsum[wid] = s;
        sp[tid] = s - pv;   // warp-local exclusive
    }
    __syncthreads();
    if (tid < 128) {
        int base = 0;
        #pragma unroll
        for (int w = 0; w < 4; w++) base += (wid > w) ? wsum[w] : 0;
        sp[tid] += base;
    }
    __syncthreads();

    int j = blockIdx.x * blockDim.x + threadIdx.x;
    if (j < NN) {
        g_rowptr[j] += sp[j >> 10];
    }
    if (j < NN * 8) {
        int row = j >> 3;
        float dv = __ldg(&g_dinv[row]);
        float4 p0 = __ldg(&((const float4*)x)[j * 2]);
        float4 p1 = __ldg(&((const float4*)x)[j * 2 + 1]);
        float f[8] = { dv*p0.x, dv*p0.y, dv*p0.z, dv*p0.w,
                       dv*p1.x, dv*p1.y, dv*p1.z, dv*p1.w };
        g_xh[j] = pack8(f);
    }
}

// atomic-free scatter: slot = rowptr[dst] + saved local offset
__global__ void k_scatter(const void* __restrict__ ei) {
    int e = blockIdx.x * blockDim.x + threadIdx.x;
    int is64 = g_is64;
    if (e < NE) {
        int src = is64 ? ((const int*)ei)[2 * (long long)e]
                       : ((const int*)ei)[e];
        int packed = g_eoff[e];
        int dst = packed >> 10;
        int off = packed & 1023;
        int pos = __ldg(&g_rowptr[dst]) + off;
        g_src[pos] = src;
    }
}

// ---------------- propagation: warp = 4 x 8-lane groups, 4 edges/iter ----------
// Rows pre-scaled: stored v = dinv*h.  t = sum v[src] + v[row].
// PASS 1: xh -> h1 = pack(dv^2 * t)
// PASS 2: h1 -> h2 = pack(dv^2 * t)
// PASS 3: h2 -> g_ach = relu(0.1x + 0.3*rdv*(v1+v2) + 0.3*dv*t)
template <int PASS>
__global__ void k_spmm(const float* __restrict__ x) {
    int row  = blockIdx.x * (blockDim.x >> 5) + (threadIdx.x >> 5);
    if (row >= NN) return;
    int lane = threadIdx.x & 31;
    int sub  = lane >> 3;       // edge slot 0..3
    int l    = lane & 7;        // uint4 index within 128B row

    const uint4* hin = (PASS == 1) ? g_xh : (PASS == 2) ? g_h1 : g_h2;

    int beg = g_rowptr[row];
    int end = g_rowptr[row + 1];
    float dv = g_dinv[row];

    float a[8];
    {   // self term: + v[row], counted once (sub 0)
        uint4 sv = __ldg(&hin[row * 8 + l]);
        float f[8]; unpack8(sv, f);
        float m0 = (sub == 0) ? 1.f : 0.f;
        #pragma unroll
        for (int i = 0; i < 8; i++) a[i] = m0 * f[i];
    }

    // simple loop with index-only prefetch (gather consumed immediately)
    int e  = beg;
    int ee = e + sub;
    int s  = (ee < end) ? __ldg(&g_src[ee]) : row;
    float m = (ee < end) ? 1.f : 0.f;
    while (e < end) {
        int en = e + 4;
        int s2 = row; float m2 = 0.f;
        int ee2 = en + sub;
        if (ee2 < end) { s2 = __ldg(&g_src[ee2]); m2 = 1.f; }
        uint4 v = __ldg(&hin[s * 8 + l]);
        float f[8]; unpack8(v, f);
        #pragma unroll
        for (int i = 0; i < 8; i++) a[i] = fmaf(m, f[i], a[i]);
        s = s2; m = m2; e = en;
    }

    #pragma unroll
    for (int i = 0; i < 8; i++) {
        a[i] += __shfl_xor_sync(0xffffffffu, a[i], 8);
        a[i] += __shfl_xor_sync(0xffffffffu, a[i], 16);
    }

    if (sub == 0) {
        int o = row * 8 + l;
        if (PASS != 3) {
            float hv[8]; float dv2 = dv * dv;
            #pragma unroll
            for (int i = 0; i < 8; i++) hv[i] = dv2 * a[i];
            ((PASS == 1) ? g_h1 : g_h2)[o] = pack8(hv);
        } else {
            // out = 0.1x + 0.3*(h1 + h2 + h3); stored v = dinv*h so h = rdv*v
            float rdv = __frcp_rn(dv);
            float c1 = COEF_C * rdv;      // for v1+v2
            float c3 = COEF_C * dv;       // h3 = dv * t
            float v1[8], v2[8];
            unpack8(__ldg(&g_h1[o]), v1);
            unpack8(__ldg(&g_h2[o]), v2);
            float4 x0 = __ldg(&((const float4*)x)[o * 2]);
            float4 x1 = __ldg(&((const float4*)x)[o * 2 + 1]);
            float xf[8] = { x0.x, x0.y, x0.z, x0.w, x1.x, x1.y, x1.z, x1.w };
            float rv[8];
            #pragma unroll
            for (int i = 0; i < 8; i++) {
                float t = ALPHA_C * xf[i] + c1 * (v1[i] + v2[i]) + c3 * a[i];
                rv[i] = fmaxf(t, 0.f);
            }
            g_ach[o] = pack8(rv);
        }
    }
}

// mean conv over original edges on relu(out) (pre-relu'd fp16) + residual + relu
__global__ void k_mean(const float* __restrict__ x, float* __restrict__ out) {
    int row  = blockIdx.x * (blockDim.x >> 5) + (threadIdx.x >> 5);
    if (row >= NN) return;
    int lane = threadIdx.x & 31;
    int sub  = lane >> 3;
    int l    = lane & 7;

    int beg = g_rowptr[row];
    int end = g_rowptr[row + 1];

    float a[8] = {0.f, 0.f, 0.f, 0.f, 0.f, 0.f, 0.f, 0.f};

    int e  = beg;
    int ee = e + sub;
    int s  = (ee < end) ? __ldg(&g_src[ee]) : row;
    float m = (ee < end) ? 1.f : 0.f;
    while (e < end) {
        int en = e + 4;
        int s2 = row; float m2 = 0.f;
        int ee2 = en + sub;
        if (ee2 < end) { s2 = __ldg(&g_src[ee2]); m2 = 1.f; }
        uint4 v = __ldg(&g_ach[s * 8 + l]);
        float f[8]; unpack8(v, f);
        #pragma unroll
        for (int i = 0; i < 8; i++) a[i] = fmaf(m, f[i], a[i]);
        s = s2; m = m2; e = en;
    }

    #pragma unroll
    for (int i = 0; i < 8; i++) {
        a[i] += __shfl_xor_sync(0xffffffffu, a[i], 8);
        a[i] += __shfl_xor_sync(0xffffffffu, a[i], 16);
    }

    if (sub == 0) {
        float inv = 1.0f / fmaxf((float)(end - beg), 1.0f);
        int o = row * 8 + l;
        float4 x0 = __ldg(&((const float4*)x)[o * 2]);
        float4 x1 = __ldg(&((const float4*)x)[o * 2 + 1]);
        float4 r0, r1;
        r0.x = fmaxf(a[0] * inv + x0.x, 0.f);
        r0.y = fmaxf(a[1] * inv + x0.y, 0.f);
        r0.z = fmaxf(a[2] * inv + x0.z, 0.f);
        r0.w = fmaxf(a[3] * inv + x0.w, 0.f);
        r1.x = fmaxf(a[4] * inv + x1.x, 0.f);
        r1.y = fmaxf(a[5] * inv + x1.y, 0.f);
        r1.z = fmaxf(a[6] * inv + x1.z, 0.f);
        r1.w = fmaxf(a[7] * inv + x1.w, 0.f);
        ((float4*)out)[o * 2]     = r0;
        ((float4*)out)[o * 2 + 1] = r1;
    }
}

// ---------------- launch ----------------
extern "C" void kernel_launch(void* const* d_in, const int* in_sizes, int n_in,
                              void* d_out, int out_size) {
    const float* x  = (const float*)d_in[0];
    const void*  ei = (const void*)d_in[1];
    float* out = (float*)d_out;

    k_prep<<<1, 32>>>((const int*)ei);
    k_hist<<<(NE + 255) / 256, 256>>>(ei);
    int nb = (NN + 1023) / 1024;   // 98
    k_scan_local<<<nb, 1024>>>();
    k_finalize<<<(NN * 8 + 255) / 256, 256>>>(x);
    k_scatter<<<(NE + 255) / 256, 256>>>(ei);

    const int WPB = 8;                        // warps (rows) per block
    int grid = (NN + WPB - 1) / WPB;          // 12500
    // SSG hops: out = 0.1*x + 0.3*(A x + A^2 x + A^3 x), acc-free
    k_spmm<1><<<grid, WPB * 32>>>(x);         // xh -> h1
    k_spmm<2><<<grid, WPB * 32>>>(x);         // h1 -> h2
    k_spmm<3><<<grid, WPB * 32>>>(x);         // h2 -> relu(out) -> g_ach
    // mean conv on relu(out) + residual + relu
    k_mean<<<grid, WPB * 32>>>(x, out);
}

// round 15
// speedup vs baseline: 1.1435x; 1.0142x over previous
#include <cuda_runtime.h>
#include <cuda_fp16.h>
#include <cstdint>

#define NN   100000
#define NE   1600000
#define ALPHA_C 0.1f
#define COEF_C  0.3f            // (1-ALPHA)/K = 0.9/3

// ---------------- scratch (device globals: no allocation allowed) ----------------
__device__ int   g_is64;             // 1 if edge_index is int64, 0 if int32
__device__ int   g_cnt[NN];          // in-degree; zero-init at load, re-zeroed in scan
__device__ int   g_rowptr[NN + 1];   // CSR row pointers by dst
__device__ float g_dinv[NN];         // 1/sqrt(deg+1)
__device__ int   g_part[128];        // scan partials (98 blocks)
__device__ int   g_eoff[NE];         // packed (dst<<10 | local offset) per edge
__device__ int   g_src[NE];          // CSR: src per edge (sorted by dst), 4B
__device__ uint4 g_xh [NN * 8];      // dinv*x  in fp16 (row = 8 uint4 = 128B)
__device__ uint4 g_h1 [NN * 8];      // dinv*h1 in fp16
__device__ uint4 g_h2 [NN * 8];      // dinv*h2 in fp16
__device__ uint4 g_ach[NN * 8];      // relu(out) in fp16 (for mean pass)

// ---------------- fp16 pack/unpack helpers ----------------
__device__ __forceinline__ void unpack8(uint4 v, float* f) {
    float2 t;
    t = __half22float2(*(__half2*)&v.x); f[0] = t.x; f[1] = t.y;
    t = __half22float2(*(__half2*)&v.y); f[2] = t.x; f[3] = t.y;
    t = __half22float2(*(__half2*)&v.z); f[4] = t.x; f[5] = t.y;
    t = __half22float2(*(__half2*)&v.w); f[6] = t.x; f[7] = t.y;
}
__device__ __forceinline__ uint4 pack8(const float* f) {
    uint4 u; __half2 h;
    h = __floats2half2_rn(f[0], f[1]); u.x = *(unsigned*)&h;
    h = __floats2half2_rn(f[2], f[3]); u.y = *(unsigned*)&h;
    h = __floats2half2_rn(f[4], f[5]); u.z = *(unsigned*)&h;
    h = __floats2half2_rn(f[6], f[7]); u.w = *(unsigned*)&h;
    return u;
}

// ---------------- prep: detect edge dtype (warp-parallel, ~1 round trip) -------
__global__ void k_prep(const int* __restrict__ ei32) {
    int lane = threadIdx.x & 31;
    // odd words 1..127: int64 values <100000 -> high words all zero
    int w0 = __ldg(&ei32[2 * lane + 1]);
    int w1 = __ldg(&ei32[2 * lane + 65]);
    int z = (w0 == 0) + (w1 == 0);
    #pragma unroll
    for (int off = 16; off > 0; off >>= 1)
        z += __shfl_xor_sync(0xffffffffu, z, off);
    if (lane == 0) {
        g_is64 = (z >= 60) ? 1 : 0;
        g_rowptr[NN] = NE;
    }
}

// ---------------- CSR build (2 edges per thread) ----------------
// hist records packed (dst, local offset) so scatter needs no atomics.
// int64 path: int4 at element (NE/2 + t) = words 2NE+4t..+3 (two dst pairs).
// int32 path: int2 at element (NE/2 + t) = words NE+2t, NE+2t+1.
__global__ void k_hist(const void* __restrict__ ei) {
    int t = blockIdx.x * blockDim.x + threadIdx.x;
    int is64 = g_is64;
    if (t < NE / 2) {
        int d0, d1;
        if (is64) {
            int4 w = __ldg(&((const int4*)ei)[NE / 2 + t]);
            d0 = w.x; d1 = w.z;
        } else {
            int2 w = __ldg(&((const int2*)ei)[NE / 2 + t]);
            d0 = w.x; d1 = w.y;
        }
        int o0 = atomicAdd(&g_cnt[d0], 1);
        int o1 = atomicAdd(&g_cnt[d1], 1);
        ((int2*)g_eoff)[t] = make_int2((d0 << 10) | o0, (d1 << 10) | o1);
    }
}

// 1024-thread block scan via shuffles; also computes dinv and re-zeroes cnt
__global__ void k_scan_local() {
    __shared__ int wsum[32];
    int tid  = threadIdx.x;
    int lane = tid & 31, wid = tid >> 5;
    int i = blockIdx.x * 1024 + tid;
    int v = (i < NN) ? g_cnt[i] : 0;
    int s = v;
    #pragma unroll
    for (int off = 1; off < 32; off <<= 1) {
        int t = __shfl_up_sync(0xffffffffu, s, off);
        if (lane >= off) s += t;
    }
    if (lane == 31) wsum[wid] = s;
    __syncthreads();
    if (wid == 0) {
        int ws = wsum[lane];
        #pragma unroll
        for (int off = 1; off < 32; off <<= 1) {
            int t = __shfl_up_sync(0xffffffffu, ws, off);
            if (lane >= off) ws += t;
        }
        wsum[lane] = ws;
    }
    __syncthreads();
    int incl = s + (wid ? wsum[wid - 1] : 0);
    if (i < NN) {
        g_rowptr[i] = incl - v;             // local exclusive
        g_dinv[i] = rsqrtf((float)(v + 1)); // +1 self loop
        g_cnt[i] = 0;                       // clean for next replay
    }
    if (tid == 1023) g_part[blockIdx.x] = incl;
}

// finalize: shuffle-scan the 98 partials per block, fix rowptr,
// AND convert x -> fp16 pre-scaled by dinv[row].  grid = NN*8 threads.
__global__ void k_finalize(const float* __restrict__ x) {
    __shared__ int wsum[8];
    __shared__ int sp[128];
    int tid  = threadIdx.x;
    int lane = tid & 31, wid = tid >> 5;
    if (tid < 128) {
        int pv = (tid < 98) ? g_part[tid] : 0;
        int s = pv;
        #pragma unroll
        for (int off = 1; off < 32; off <<= 1) {
            int t = __shfl_up_sync(0xffffffffu, s, off);
            if (lane >= off) s += t;
        }
        if (lane == 31) wsum[wid] = s;
        sp[tid] = s - pv;   // warp-local exclusive
    }
    __syncthreads();
    if (tid < 128) {
        int base = 0;
        #pragma unroll
        for (int w = 0; w < 4; w++) base += (wid > w) ? wsum[w] : 0;
        sp[tid] += base;
    }
    __syncthreads();

    int j = blockIdx.x * blockDim.x + threadIdx.x;
    if (j < NN) {
        g_rowptr[j] += sp[j >> 10];
    }
    if (j < NN * 8) {
        int row = j >> 3;
        float dv = __ldg(&g_dinv[row]);
        float4 p0 = __ldg(&((const float4*)x)[j * 2]);
        float4 p1 = __ldg(&((const float4*)x)[j * 2 + 1]);
        float f[8] = { dv*p0.x, dv*p0.y, dv*p0.z, dv*p0.w,
                       dv*p1.x, dv*p1.y, dv*p1.z, dv*p1.w };
        g_xh[j] = pack8(f);
    }
}

// atomic-free scatter, 2 edges per thread: slot = rowptr[dst] + saved offset
__global__ void k_scatter(const void* __restrict__ ei) {
    int t = blockIdx.x * blockDim.x + threadIdx.x;
    int is64 = g_is64;
    if (t < NE / 2) {
        int s0, s1;
        if (is64) {
            int4 w = __ldg(&((const int4*)ei)[t]);   // words 4t..4t+3: two src pairs
            s0 = w.x; s1 = w.z;
        } else {
            int2 w = __ldg(&((const int2*)ei)[t]);   // words 2t, 2t+1
            s0 = w.x; s1 = w.y;
        }
        int2 p = __ldg(&((const int2*)g_eoff)[t]);
        g_src[__ldg(&g_rowptr[p.x >> 10]) + (p.x & 1023)] = s0;
        g_src[__ldg(&g_rowptr[p.y >> 10]) + (p.y & 1023)] = s1;
    }
}

// ---------------- propagation: warp = 4 x 8-lane groups, 4 edges/iter ----------
// Rows pre-scaled: stored v = dinv*h.  t = sum v[src] + v[row].
// PASS 1: xh -> h1 = pack(dv^2 * t)
// PASS 2: h1 -> h2 = pack(dv^2 * t)
// PASS 3: h2 -> g_ach = relu(0.1x + 0.3*rdv*(v1+v2) + 0.3*dv*t)
template <int PASS>
__global__ void k_spmm(const float* __restrict__ x) {
    int row  = blockIdx.x * (blockDim.x >> 5) + (threadIdx.x >> 5);
    if (row >= NN) return;
    int lane = threadIdx.x & 31;
    int sub  = lane >> 3;       // edge slot 0..3
    int l    = lane & 7;        // uint4 index within 128B row

    const uint4* hin = (PASS == 1) ? g_xh : (PASS == 2) ? g_h1 : g_h2;

    int beg = g_rowptr[row];
    int end = g_rowptr[row + 1];
    float dv = g_dinv[row];

    float a[8];
    {   // self term: + v[row], counted once (sub 0)
        uint4 sv = __ldg(&hin[row * 8 + l]);
        float f[8]; unpack8(sv, f);
        float m0 = (sub == 0) ? 1.f : 0.f;
        #pragma unroll
        for (int i = 0; i < 8; i++) a[i] = m0 * f[i];
    }

    // simple loop with index-only prefetch (gather consumed immediately)
    int e  = beg;
    int ee = e + sub;
    int s  = (ee < end) ? __ldg(&g_src[ee]) : row;
    float m = (ee < end) ? 1.f : 0.f;
    while (e < end) {
        int en = e + 4;
        int s2 = row; float m2 = 0.f;
        int ee2 = en + sub;
        if (ee2 < end) { s2 = __ldg(&g_src[ee2]); m2 = 1.f; }
        uint4 v = __ldg(&hin[s * 8 + l]);
        float f[8]; unpack8(v, f);
        #pragma unroll
        for (int i = 0; i < 8; i++) a[i] = fmaf(m, f[i], a[i]);
        s = s2; m = m2; e = en;
    }

    #pragma unroll
    for (int i = 0; i < 8; i++) {
        a[i] += __shfl_xor_sync(0xffffffffu, a[i], 8);
        a[i] += __shfl_xor_sync(0xffffffffu, a[i], 16);
    }

    if (sub == 0) {
        int o = row * 8 + l;
        if (PASS != 3) {
            float hv[8]; float dv2 = dv * dv;
            #pragma unroll
            for (int i = 0; i < 8; i++) hv[i] = dv2 * a[i];
            ((PASS == 1) ? g_h1 : g_h2)[o] = pack8(hv);
        } else {
            // out = 0.1x + 0.3*(h1 + h2 + h3); stored v = dinv*h so h = rdv*v
            float rdv = __frcp_rn(dv);
            float c1 = COEF_C * rdv;      // for v1+v2
            float c3 = COEF_C * dv;       // h3 = dv * t
            float v1[8], v2[8];
            unpack8(__ldg(&g_h1[o]), v1);
            unpack8(__ldg(&g_h2[o]), v2);
            float4 x0 = __ldg(&((const float4*)x)[o * 2]);
            float4 x1 = __ldg(&((const float4*)x)[o * 2 + 1]);
            float xf[8] = { x0.x, x0.y, x0.z, x0.w, x1.x, x1.y, x1.z, x1.w };
            float rv[8];
            #pragma unroll
            for (int i = 0; i < 8; i++) {
                float t = ALPHA_C * xf[i] + c1 * (v1[i] + v2[i]) + c3 * a[i];
                rv[i] = fmaxf(t, 0.f);
            }
            g_ach[o] = pack8(rv);
        }
    }
}

// mean conv over original edges on relu(out) (pre-relu'd fp16) + residual + relu
__global__ void k_mean(const float* __restrict__ x, float* __restrict__ out) {
    int row  = blockIdx.x * (blockDim.x >> 5) + (threadIdx.x >> 5);
    if (row >= NN) return;
    int lane = threadIdx.x & 31;
    int sub  = lane >> 3;
    int l    = lane & 7;

    int beg = g_rowptr[row];
    int end = g_rowptr[row + 1];

    float a[8] = {0.f, 0.f, 0.f, 0.f, 0.f, 0.f, 0.f, 0.f};

    int e  = beg;
    int ee = e + sub;
    int s  = (ee < end) ? __ldg(&g_src[ee]) : row;
    float m = (ee < end) ? 1.f : 0.f;
    while (e < end) {
        int en = e + 4;
        int s2 = row; float m2 = 0.f;
        int ee2 = en + sub;
        if (ee2 < end) { s2 = __ldg(&g_src[ee2]); m2 = 1.f; }
        uint4 v = __ldg(&g_ach[s * 8 + l]);
        float f[8]; unpack8(v, f);
        #pragma unroll
        for (int i = 0; i < 8; i++) a[i] = fmaf(m, f[i], a[i]);
        s = s2; m = m2; e = en;
    }

    #pragma unroll
    for (int i = 0; i < 8; i++) {
        a[i] += __shfl_xor_sync(0xffffffffu, a[i], 8);
        a[i] += __shfl_xor_sync(0xffffffffu, a[i], 16);
    }

    if (sub == 0) {
        float inv = 1.0f / fmaxf((float)(end - beg), 1.0f);
        int o = row * 8 + l;
        float4 x0 = __ldg(&((const float4*)x)[o * 2]);
        float4 x1 = __ldg(&((const float4*)x)[o * 2 + 1]);
        float4 r0, r1;
        r0.x = fmaxf(a[0] * inv + x0.x, 0.f);
        r0.y = fmaxf(a[1] * inv + x0.y, 0.f);
        r0.z = fmaxf(a[2] * inv + x0.z, 0.f);
        r0.w = fmaxf(a[3] * inv + x0.w, 0.f);
        r1.x = fmaxf(a[4] * inv + x1.x, 0.f);
        r1.y = fmaxf(a[5] * inv + x1.y, 0.f);
        r1.z = fmaxf(a[6] * inv + x1.z, 0.f);
        r1.w = fmaxf(a[7] * inv + x1.w, 0.f);
        ((float4*)out)[o * 2]     = r0;
        ((float4*)out)[o * 2 + 1] = r1;
    }
}

// ---------------- launch ----------------
extern "C" void kernel_launch(void* const* d_in, const int* in_sizes, int n_in,
                              void* d_out, int out_size) {
    const float* x  = (const float*)d_in[0];
    const void*  ei = (const void*)d_in[1];
    float* out = (float*)d_out;

    k_prep<<<1, 32>>>((const int*)ei);
    k_hist<<<(NE / 2 + 255) / 256, 256>>>(ei);
    int nb = (NN + 1023) / 1024;   // 98
    k_scan_local<<<nb, 1024>>>();
    k_finalize<<<(NN * 8 + 255) / 256, 256>>>(x);
    k_scatter<<<(NE / 2 + 255) / 256, 256>>>(ei);

    const int WPB = 8;                        // warps (rows) per block
    int grid = (NN + WPB - 1) / WPB;          // 12500
    // SSG hops: out = 0.1*x + 0.3*(A x + A^2 x + A^3 x), acc-free
    k_spmm<1><<<grid, WPB * 32>>>(x);         // xh -> h1
    k_spmm<2><<<grid, WPB * 32>>>(x);         // h1 -> h2
    k_spmm<3><<<grid, WPB * 32>>>(x);         // h2 -> relu(out) -> g_ach
    // mean conv on relu(out) + residual + relu
    k_mean<<<grid, WPB * 32>>>(x, out);
}

// round 17
// speedup vs baseline: 1.1648x; 1.0187x over previous
#include <cuda_runtime.h>
#include <cuda_fp16.h>
#include <cstdint>

#define NN   100000
#define NE   1600000
#define ALPHA_C 0.1f
#define COEF_C  0.3f            // (1-ALPHA)/K = 0.9/3

// ---------------- scratch (device globals: no allocation allowed) ----------------
__device__ int   g_cnt[NN];          // in-degree; zero-init at load, re-zeroed in scan
__device__ int   g_rowptr[NN + 1];   // CSR row pointers by dst
__device__ float g_dinv[NN];         // 1/sqrt(deg+1)
__device__ int   g_part[128];        // scan partials (98 blocks)
__device__ int   g_eoff[NE];         // packed (dst<<10 | local offset) per edge
__device__ int   g_src[NE];          // CSR: src per edge (sorted by dst), 4B
__device__ uint4 g_xh [NN * 8];      // dinv*x  in fp16 (row = 8 uint4 = 128B)
__device__ uint4 g_h1 [NN * 8];      // dinv*h1 in fp16
__device__ uint4 g_h2 [NN * 8];      // dinv*h2 in fp16
__device__ uint4 g_ach[NN * 8];      // relu(out) in fp16 (for mean pass)

// ---------------- fp16 pack/unpack helpers ----------------
__device__ __forceinline__ void unpack8(uint4 v, float* f) {
    float2 t;
    t = __half22float2(*(__half2*)&v.x); f[0] = t.x; f[1] = t.y;
    t = __half22float2(*(__half2*)&v.y); f[2] = t.x; f[3] = t.y;
    t = __half22float2(*(__half2*)&v.z); f[4] = t.x; f[5] = t.y;
    t = __half22float2(*(__half2*)&v.w); f[6] = t.x; f[7] = t.y;
}
__device__ __forceinline__ uint4 pack8(const float* f) {
    uint4 u; __half2 h;
    h = __floats2half2_rn(f[0], f[1]); u.x = *(unsigned*)&h;
    h = __floats2half2_rn(f[2], f[3]); u.y = *(unsigned*)&h;
    h = __floats2half2_rn(f[4], f[5]); u.z = *(unsigned*)&h;
    h = __floats2half2_rn(f[6], f[7]); u.w = *(unsigned*)&h;
    return u;
}

// per-block dtype detection: int64 little-endian values < 100000 -> odd words 0.
// All blocks read the same 512B (L2 broadcast). Uniform barrier pattern.
__device__ __forceinline__ int detect_is64(const int* __restrict__ ei32, int* s_flag) {
    if (threadIdx.x < 32) {
        int lane = threadIdx.x;
        int z = (__ldg(&ei32[2 * lane + 1]) == 0) + (__ldg(&ei32[2 * lane + 65]) == 0);
        #pragma unroll
        for (int off = 16; off > 0; off >>= 1)
            z += __shfl_xor_sync(0xffffffffu, z, off);
        if (lane == 0) *s_flag = (z >= 60) ? 1 : 0;
    }
    __syncthreads();
    return *s_flag;
}

// ---------------- CSR build (2 edges per thread) ----------------
// hist records packed (dst, local offset) so scatter needs no atomics.
__global__ void k_hist(const void* __restrict__ ei) {
    __shared__ int s_is64;
    int is64 = detect_is64((const int*)ei, &s_is64);
    int t = blockIdx.x * blockDim.x + threadIdx.x;
    if (t < NE / 2) {
        int d0, d1;
        if (is64) {
            int4 w = __ldg(&((const int4*)ei)[NE / 2 + t]);  // two (lo,hi) dst pairs
            d0 = w.x; d1 = w.z;
        } else {
            int2 w = __ldg(&((const int2*)ei)[NE / 2 + t]);
            d0 = w.x; d1 = w.y;
        }
        int o0 = atomicAdd(&g_cnt[d0], 1);
        int o1 = atomicAdd(&g_cnt[d1], 1);
        ((int2*)g_eoff)[t] = make_int2((d0 << 10) | o0, (d1 << 10) | o1);
    }
}

// 1024-thread block scan via shuffles; also computes dinv and re-zeroes cnt
__global__ void k_scan_local() {
    __shared__ int wsum[32];
    int tid  = threadIdx.x;
    int lane = tid & 31, wid = tid >> 5;
    int i = blockIdx.x * 1024 + tid;
    int v = (i < NN) ? g_cnt[i] : 0;
    int s = v;
    #pragma unroll
    for (int off = 1; off < 32; off <<= 1) {
        int t = __shfl_up_sync(0xffffffffu, s, off);
        if (lane >= off) s += t;
    }
    if (lane == 31) wsum[wid] = s;
    __syncthreads();
    if (wid == 0) {
        int ws = wsum[lane];
        #pragma unroll
        for (int off = 1; off < 32; off <<= 1) {
            int t = __shfl_up_sync(0xffffffffu, ws, off);
            if (lane >= off) ws += t;
        }
        wsum[lane] = ws;
    }
    __syncthreads();
    int incl = s + (wid ? wsum[wid - 1] : 0);
    if (i < NN) {
        g_rowptr[i] = incl - v;             // local exclusive
        g_dinv[i] = rsqrtf((float)(v + 1)); // +1 self loop
        g_cnt[i] = 0;                       // clean for next replay
    }
    if (tid == 1023) g_part[blockIdx.x] = incl;
}

// fix: each block adds the sum of partials before it (reduction, not a scan).
// Uniform barrier pattern across all 1024 threads.
__global__ void k_fix() {
    __shared__ int w[4];
    __shared__ int sbase;
    int tid = threadIdx.x;
    if (tid < 128) {
        int p = (tid < blockIdx.x && tid < 98) ? g_part[tid] : 0;
        #pragma unroll
        for (int off = 16; off > 0; off >>= 1)
            p += __shfl_xor_sync(0xffffffffu, p, off);
        if ((tid & 31) == 0) w[tid >> 5] = p;
    }
    __syncthreads();                         // all threads
    if (tid == 0) sbase = w[0] + w[1] + w[2] + w[3];
    __syncthreads();                         // all threads
    int i = blockIdx.x * 1024 + tid;
    if (i < NN) g_rowptr[i] += sbase;
    if (i == NN - 1) g_rowptr[NN] = NE;
}

// fused: atomic-free scatter (2 edges/thread) + x -> fp16*dinv conversion
// (one uint4/thread).  NE/2 == NN*8 == 800000 threads covers both.
__global__ void k_scatter(const void* __restrict__ ei, const float* __restrict__ x) {
    __shared__ int s_is64;
    int is64 = detect_is64((const int*)ei, &s_is64);
    int t = blockIdx.x * blockDim.x + threadIdx.x;
    if (t < NE / 2) {
        int s0, s1;
        if (is64) {
            int4 w = __ldg(&((const int4*)ei)[t]);   // two (lo,hi) src pairs
            s0 = w.x; s1 = w.z;
        } else {
            int2 w = __ldg(&((const int2*)ei)[t]);
            s0 = w.x; s1 = w.y;
        }
        int2 p = __ldg(&((const int2*)g_eoff)[t]);
        g_src[__ldg(&g_rowptr[p.x >> 10]) + (p.x & 1023)] = s0;
        g_src[__ldg(&g_rowptr[p.y >> 10]) + (p.y & 1023)] = s1;
    }
    if (t < NN * 8) {
        int row = t >> 3;
        float dv = __ldg(&g_dinv[row]);
        float4 p0 = __ldg(&((const float4*)x)[t * 2]);
        float4 p1 = __ldg(&((const float4*)x)[t * 2 + 1]);
        float f[8] = { dv*p0.x, dv*p0.y, dv*p0.z, dv*p0.w,
                       dv*p1.x, dv*p1.y, dv*p1.z, dv*p1.w };
        g_xh[t] = pack8(f);
    }
}

// ---------------- propagation: warp = 4 x 8-lane groups, 4 edges/iter ----------
// Rows pre-scaled: stored v = dinv*h.  t = sum v[src] + v[row].
// PASS 1: xh -> h1 = pack(dv^2 * t)
// PASS 2: h1 -> h2 = pack(dv^2 * t)
// PASS 3: h2 -> g_ach = relu(0.1x + 0.3*rdv*(v1+v2) + 0.3*dv*t)
template <int PASS>
__global__ void k_spmm(const float* __restrict__ x) {
    int row  = blockIdx.x * (blockDim.x >> 5) + (threadIdx.x >> 5);
    if (row >= NN) return;
    int lane = threadIdx.x & 31;
    int sub  = lane >> 3;       // edge slot 0..3
    int l    = lane & 7;        // uint4 index within 128B row

    const uint4* hin = (PASS == 1) ? g_xh : (PASS == 2) ? g_h1 : g_h2;

    int beg = g_rowptr[row];
    int end = g_rowptr[row + 1];
    float dv = g_dinv[row];

    float a[8];
    {   // self term: + v[row], counted once (sub 0)
        uint4 sv = __ldg(&hin[row * 8 + l]);
        float f[8]; unpack8(sv, f);
        float m0 = (sub == 0) ? 1.f : 0.f;
        #pragma unroll
        for (int i = 0; i < 8; i++) a[i] = m0 * f[i];
    }

    // simple loop with index-only prefetch (gather consumed immediately)
    int e  = beg;
    int ee = e + sub;
    int s  = (ee < end) ? __ldg(&g_src[ee]) : row;
    float m = (ee < end) ? 1.f : 0.f;
    while (e < end) {
        int en = e + 4;
        int s2 = row; float m2 = 0.f;
        int ee2 = en + sub;
        if (ee2 < end) { s2 = __ldg(&g_src[ee2]); m2 = 1.f; }
        uint4 v = __ldg(&hin[s * 8 + l]);
        float f[8]; unpack8(v, f);
        #pragma unroll
        for (int i = 0; i < 8; i++) a[i] = fmaf(m, f[i], a[i]);
        s = s2; m = m2; e = en;
    }

    #pragma unroll
    for (int i = 0; i < 8; i++) {
        a[i] += __shfl_xor_sync(0xffffffffu, a[i], 8);
        a[i] += __shfl_xor_sync(0xffffffffu, a[i], 16);
    }

    if (sub == 0) {
        int o = row * 8 + l;
        if (PASS != 3) {
            float hv[8]; float dv2 = dv * dv;
            #pragma unroll
            for (int i = 0; i < 8; i++) hv[i] = dv2 * a[i];
            ((PASS == 1) ? g_h1 : g_h2)[o] = pack8(hv);
        } else {
            // out = 0.1x + 0.3*(h1 + h2 + h3); stored v = dinv*h so h = rdv*v
            float rdv = __frcp_rn(dv);
            float c1 = COEF_C * rdv;      // for v1+v2
            float c3 = COEF_C * dv;       // h3 = dv * t
            float v1[8], v2[8];
            unpack8(__ldg(&g_h1[o]), v1);
            unpack8(__ldg(&g_h2[o]), v2);
            float4 x0 = __ldg(&((const float4*)x)[o * 2]);
            float4 x1 = __ldg(&((const float4*)x)[o * 2 + 1]);
            float xf[8] = { x0.x, x0.y, x0.z, x0.w, x1.x, x1.y, x1.z, x1.w };
            float rv[8];
            #pragma unroll
            for (int i = 0; i < 8; i++) {
                float t = ALPHA_C * xf[i] + c1 * (v1[i] + v2[i]) + c3 * a[i];
                rv[i] = fmaxf(t, 0.f);
            }
            g_ach[o] = pack8(rv);
        }
    }
}

// mean conv over original edges on relu(out) (pre-relu'd fp16) + residual + relu
__global__ void k_mean(const float* __restrict__ x, float* __restrict__ out) {
    int row  = blockIdx.x * (blockDim.x >> 5) + (threadIdx.x >> 5);
    if (row >= NN) return;
    int lane = threadIdx.x & 31;
    int sub  = lane >> 3;
    int l    = lane & 7;

    int beg = g_rowptr[row];
    int end = g_rowptr[row + 1];

    float a[8] = {0.f, 0.f, 0.f, 0.f, 0.f, 0.f, 0.f, 0.f};

    int e  = beg;
    int ee = e + sub;
    int s  = (ee < end) ? __ldg(&g_src[ee]) : row;
    float m = (ee < end) ? 1.f : 0.f;
    while (e < end) {
        int en = e + 4;
        int s2 = row; float m2 = 0.f;
        int ee2 = en + sub;
        if (ee2 < end) { s2 = __ldg(&g_src[ee2]); m2 = 1.f; }
        uint4 v = __ldg(&g_ach[s * 8 + l]);
        float f[8]; unpack8(v, f);
        #pragma unroll
        for (int i = 0; i < 8; i++) a[i] = fmaf(m, f[i], a[i]);
        s = s2; m = m2; e = en;
    }

    #pragma unroll
    for (int i = 0; i < 8; i++) {
        a[i] += __shfl_xor_sync(0xffffffffu, a[i], 8);
        a[i] += __shfl_xor_sync(0xffffffffu, a[i], 16);
    }

    if (sub == 0) {
        float inv = 1.0f / fmaxf((float)(end - beg), 1.0f);
        int o = row * 8 + l;
        float4 x0 = __ldg(&((const float4*)x)[o * 2]);
        float4 x1 = __ldg(&((const float4*)x)[o * 2 + 1]);
        float4 r0, r1;
        r0.x = fmaxf(a[0] * inv + x0.x, 0.f);
        r0.y = fmaxf(a[1] * inv + x0.y, 0.f);
        r0.z = fmaxf(a[2] * inv + x0.z, 0.f);
        r0.w = fmaxf(a[3] * inv + x0.w, 0.f);
        r1.x = fmaxf(a[4] * inv + x1.x, 0.f);
        r1.y = fmaxf(a[5] * inv + x1.y, 0.f);
        r1.z = fmaxf(a[6] * inv + x1.z, 0.f);
        r1.w = fmaxf(a[7] * inv + x1.w, 0.f);
        ((float4*)out)[o * 2]     = r0;
        ((float4*)out)[o * 2 + 1] = r1;
    }
}

// ---------------- launch ----------------
extern "C" void kernel_launch(void* const* d_in, const int* in_sizes, int n_in,
                              void* d_out, int out_size) {
    const float* x  = (const float*)d_in[0];
    const void*  ei = (const void*)d_in[1];
    float* out = (float*)d_out;

    k_hist<<<(NE / 2 + 255) / 256, 256>>>(ei);
    int nb = (NN + 1023) / 1024;   // 98
    k_scan_local<<<nb, 1024>>>();
    k_fix<<<nb, 1024>>>();
    k_scatter<<<(NE / 2 + 255) / 256, 256>>>(ei, x);

    const int WPB = 8;                        // warps (rows) per block
    int grid = (NN + WPB - 1) / WPB;          // 12500
    // SSG hops: out = 0.1*x + 0.3*(A x + A^2 x + A^3 x), acc-free
    k_spmm<1><<<grid, WPB * 32>>>(x);         // xh -> h1
    k_spmm<2><<<grid, WPB * 32>>>(x);         // h1 -> h2
    k_spmm<3><<<grid, WPB * 32>>>(x);         // h2 -> relu(out) -> g_ach
    // mean conv on relu(out) + residual + relu
    k_mean<<<grid, WPB * 32>>>(x, out);
}